// round 2
// baseline (speedup 1.0000x reference)
#include <cuda_runtime.h>
#include <cuda_bf16.h>

// out[i][k] = s_{k-1}(x_i) - s_k(x_i),  s_j(x) = relu(1 - relu(xb_j - x)/(h_j + 1e-9))
// with virtual s_{-1} = 1, s_{n_el} = 0. At most the containing interval's
// neighborhood is nonzero, so: zero-fill the row (float4), then patch <=4 columns
// around the binary-searched interval using the exact reference formula.

#define ROWS_PER_BLOCK 4
#define THREADS_PER_BLOCK 256

__global__ void __launch_bounds__(THREADS_PER_BLOCK)
hat_basis_kernel(const float* __restrict__ x_eval,
                 const float* __restrict__ x_full,
                 float* __restrict__ out,
                 int n_points, int n_nodes)
{
    const int n_el = n_nodes - 1;

    const long long row0 = (long long)blockIdx.x * ROWS_PER_BLOCK;
    const long long f0   = row0 * (long long)n_nodes;          // first flat float index of this chunk
    const long long total = (long long)n_points * (long long)n_nodes;
    long long nfl = (long long)ROWS_PER_BLOCK * n_nodes;
    if (f0 + nfl > total) nfl = total - f0;
    if (nfl <= 0) return;

    // ---- vectorized zero fill of this block's 4-row chunk ----
    // f0 is a multiple of 4 floats (ROWS_PER_BLOCK * n_nodes = 4*2049 divisible by 4),
    // so the float4 pointer is 16B-aligned.
    {
        float4* o4 = reinterpret_cast<float4*>(out + f0);
        const int n4 = (int)(nfl >> 2);
        const float4 z = make_float4(0.f, 0.f, 0.f, 0.f);
        for (int i = threadIdx.x; i < n4; i += THREADS_PER_BLOCK)
            o4[i] = z;
        // scalar tail (only possible for a ragged final chunk; not hit for 32768 rows)
        for (long long i = ((long long)n4 << 2) + threadIdx.x; i < nfl; i += THREADS_PER_BLOCK)
            out[f0 + i] = 0.f;
    }
    __syncthreads();

    // ---- sparse patch: one eval point per low thread ----
    const int r = threadIdx.x;
    if (r < ROWS_PER_BLOCK) {
        const long long row = row0 + r;
        if (row < n_points) {
            const float x = x_eval[row];

            // largest j in [0, n_el-1] with x_full[j] <= x (clamped at both ends)
            int lo = 0, hi = n_el;
            while (hi - lo > 1) {
                const int mid = (lo + hi) >> 1;
                if (__ldg(&x_full[mid]) <= x) lo = mid; else hi = mid;
            }
            const int j = lo;

            // s_k evaluated with the exact reference arithmetic for k in [j-2, j+2]
            float S[5];
#pragma unroll
            for (int t = 0; t < 5; ++t) {
                const int k = j - 2 + t;
                float s;
                if (k < 0) {
                    s = 1.0f;                 // virtual s_{-1} (and anything below)
                } else if (k >= n_el) {
                    s = 0.0f;                 // virtual s_{n_el}
                } else {
                    const float xa = __ldg(&x_full[k]);
                    const float xb = __ldg(&x_full[k + 1]);
                    const float h  = xb - xa;
                    const float l1 = fmaxf(xb - x, 0.0f);          // relu(xb - x)
                    s = fmaxf(1.0f - l1 / (h + 1e-9f), 0.0f);       // relu(1 - l1/(h+eps))
                }
                S[t] = s;
            }

            float* orow = out + row * (long long)n_nodes;
#pragma unroll
            for (int t = 1; t < 5; ++t) {
                const int c = j - 2 + t;       // columns j-1 .. j+2
                if (c >= 0 && c <= n_el)
                    orow[c] = S[t - 1] - S[t];
            }
        }
    }
}

extern "C" void kernel_launch(void* const* d_in, const int* in_sizes, int n_in,
                              void* d_out, int out_size) {
    const float* x_eval = (const float*)d_in[0];   // (n_points, 1) float32
    const float* x_full = (const float*)d_in[1];   // (n_nodes,)  float32, sorted
    float* out = (float*)d_out;

    const int n_points = in_sizes[0];
    const int n_nodes  = in_sizes[1];

    const int blocks = (n_points + ROWS_PER_BLOCK - 1) / ROWS_PER_BLOCK;
    hat_basis_kernel<<<blocks, THREADS_PER_BLOCK>>>(x_eval, x_full, out, n_points, n_nodes);
}